// round 17
// baseline (speedup 1.0000x reference)
#include <cuda_runtime.h>
#include <cuda.h>
#include <cuda_fp16.h>
#include <math.h>
#include <stdint.h>

#define BB 32
#define TT 1500
#define HH 768
#define HM1 767
#define LQ 400
#define MM (BB*LQ)                 /* 12800 */
#define FC_OFF ((size_t)MM*HH)
#define NHAT_OFF ((size_t)2*MM*HH)
#define P_MIX_C 0.15f

#define NRB 100
#define NCB 6
#define TILES1 (NRB*NCB)           /* 600 */
#define TILES_ALL (2*TILES1)       /* 1200 */
#define NCTA 296                   /* 148 SMs x 2 CTAs */

/* work-unit map: alpha -> scan -> wtrans (late-claimed units are W2
   transposes, needed only by GEMM2) */
#define NU_ALPHA BB                /* 32 */
#define U_SCAN0  NU_ALPHA          /* 32 */
#define NU_SCAN  (3*BB)            /* 96 */
#define U_WT0    (U_SCAN0 + NU_SCAN)  /* 128 */
#define NU_WT    192
#define U_NHAT   (U_WT0 + NU_WT)   /* 320 */
#define U_GEMM0  (U_NHAT + 1)      /* 321 */
#define U_TOTAL  (U_GEMM0 + TILES_ALL) /* 1521 */

// ---------------- scratch (__device__ globals, no allocs) ------------------
__device__ float g_scale[BB];
__device__ float g_nhat_part[BB];
__device__ int   g_tilectr;
__device__ int   g_ready[NRB];
__device__ int   g_wt_ready[2];
__device__ int   g_alpha_ready[BB];
__device__ int   g_scan_ready[BB];
__device__ __half g_sa[(size_t)MM * HH];
__device__ __half g_y1[(size_t)MM * HH];
__device__ __half g_w1t[(size_t)HH * HH];
__device__ __half g_w2t[(size_t)HH * HH];

// ---------------- helpers --------------------------------------------------
__device__ __forceinline__ uint32_t smem_u32(const void* p) {
    uint32_t a;
    asm("{ .reg .u64 t; cvta.to.shared.u64 t, %1; cvt.u32.u64 %0, t; }"
        : "=r"(a) : "l"(p));
    return a;
}
__device__ __forceinline__ uint32_t pack2h(__half a, __half b) {
    return (uint32_t)__half_as_ushort(a) |
           ((uint32_t)__half_as_ushort(b) << 16);
}
__device__ __forceinline__ int ld_acquire(const int* p) {
    int v;
    asm volatile("ld.global.acquire.gpu.b32 %0, [%1];" : "=r"(v) : "l"(p) : "memory");
    return v;
}

#define LDM4(r, addr) \
    asm volatile("ldmatrix.sync.aligned.m8n8.x4.shared.b16 {%0,%1,%2,%3},[%4];" \
        : "=r"((r)[0]), "=r"((r)[1]), "=r"((r)[2]), "=r"((r)[3]) : "r"(addr))

#define MMAH(d, a, b) \
    asm volatile("mma.sync.aligned.m16n8k16.row.col.f32.f16.f16.f32 " \
        "{%0,%1,%2,%3},{%4,%5,%6,%7},{%8,%9},{%0,%1,%2,%3};" \
        : "+f"((d)[0]), "+f"((d)[1]), "+f"((d)[2]), "+f"((d)[3]) \
        : "r"((a)[0]), "r"((a)[1]), "r"((a)[2]), "r"((a)[3]), \
          "r"((b)[0]), "r"((b)[1]))

#define MBAR_INIT(mbar, cnt) \
    asm volatile("mbarrier.init.shared.b64 [%0], %1;" :: "r"(mbar), "r"(cnt) : "memory")
#define MBAR_EXPECT_TX(mbar, bytes) \
    asm volatile("mbarrier.arrive.expect_tx.shared.b64 _, [%0], %1;" \
                 :: "r"(mbar), "r"(bytes) : "memory")
#define MBAR_WAIT(mbar, par) do {                                             \
    uint32_t _m = (mbar), _p = (par), _d;                                     \
    asm volatile("{\n\t.reg .pred p;\n\t"                                     \
        "mbarrier.try_wait.parity.acquire.cta.shared::cta.b64 p, [%1], %2;\n\t"\
        "selp.b32 %0, 1, 0, p;\n\t}" : "=r"(_d) : "r"(_m), "r"(_p) : "memory");\
    if (!_d) {                                                                \
        asm volatile("{\n\t.reg .pred P1;\n\t"                                \
        "WL_%=:\n\t"                                                          \
        "mbarrier.try_wait.parity.acquire.cta.shared::cta.b64 P1, [%0], %1, 0x989680;\n\t"\
        "@P1 bra.uni WD_%=;\n\tbra.uni WL_%=;\n\tWD_%=:\n\t}"                 \
        :: "r"(_m), "r"(_p) : "memory");                                      \
    } } while (0)

#define TMA2D(smemaddr, mapptr, x, y, mbar) \
    asm volatile("cp.async.bulk.tensor.2d.shared::cta.global.tile.mbarrier::complete_tx::bytes " \
                 "[%0], [%1, {%2, %3}], [%4];" \
                 :: "r"(smemaddr), "l"(mapptr), "r"(x), "r"(y), "r"(mbar) : "memory")

// ---------------------------------------------------------------------------
__global__ void reset_kernel() {
    int t = threadIdx.x;
    if (t == 0) g_tilectr = 0;
    if (t < NRB) g_ready[t] = 0;
    if (t < BB) { g_alpha_ready[t] = 0; g_scan_ready[t] = 0; }
    if (t < 2) g_wt_ready[t] = 0;
}

// ---------------------------------------------------------------------------
// Prelude work units (inside the persistent kernel; noinline keeps their
// register pressure away from the GEMM hot loop). Publishes use the
// cumulative two-stage release: syncthreads -> tid0 fence+atomicAdd.
// ---------------------------------------------------------------------------
__device__ __noinline__ void do_alpha(const float* hs, const int* lengths,
                                      int b, char* smem) {
    float* red = (float*)(smem + 64);
    int tid = threadIdx.x;
    const float* base = hs + (size_t)b * TT * HH + (HH - 1);
    float s = 0.f;
    for (int t = tid; t < TT; t += 256)
        s += 1.f / (1.f + expf(-base[(size_t)t * HH]));
    red[tid] = s;
    __syncthreads();
    for (int o = 128; o > 0; o >>= 1) {
        if (tid < o) red[tid] += red[tid + o];
        __syncthreads();
    }
    if (tid == 0) {
        float sum = red[0];
        int li = lengths[b];
        float tll = (float)(li < LQ ? li : LQ);
        g_scale[b] = tll / sum;
        float d = tll - sum;
        g_nhat_part[b] = d * d;
        __threadfence();
        atomicAdd(&g_alpha_ready[b], 1);
    }
}

__device__ __noinline__ void do_wtrans(const float* W1, const float* W2,
                                       int mat, int cb, int kg, char* smem) {
    const float* W = mat ? W2 : W1;
    int Kvalid = mat ? HH : HM1;
    __half* Wt = mat ? g_w2t : g_w1t;
    float* t = (float*)(smem + 64);      // [32][33]
    int tid = threadIdx.x, tx = tid & 31, ty = tid >> 5;
    for (int kb = kg * 6; kb < kg * 6 + 6; ++kb) {
        #pragma unroll
        for (int j = 0; j < 32; j += 8) {
            int k = kb * 32 + ty + j;
            t[(ty + j) * 33 + tx] = (k < Kvalid) ? W[(size_t)k * HH + cb * 32 + tx] : 0.f;
        }
        __syncthreads();
        #pragma unroll
        for (int j = 0; j < 32; j += 8) {
            int nn = cb * 32 + ty + j;
            int kk = kb * 32 + tx;
            Wt[(size_t)nn * HH + kk] = __float2half_rn(t[tx * 33 + ty + j]);
        }
        __syncthreads();
    }
    if (tid == 0) { __threadfence(); atomicAdd(&g_wt_ready[mat], 1); }
}

__device__ __noinline__ void do_scan(const float* hs, int b, int xb, char* smem) {
    float* salpha = (float*)(smem + 64);   // 400 floats
    int tid = threadIdx.x;
    if (tid == 0)
        while (ld_acquire(&g_alpha_ready[b]) < 1) __nanosleep(128);
    __syncthreads();
    float scale = g_scale[b];
    const float* hb = hs + (size_t)b * TT * HH;
    for (int t = tid; t < LQ; t += 256)
        salpha[t] = scale / (1.f + expf(-hb[(size_t)t * HH + (HH - 1)]));
    __syncthreads();

    int f = xb * 256 + tid;               // 0..767
    bool valid = (f < HM1);
    const float* hcol = hb + f;
    size_t obase = (size_t)b * LQ * HH + f;

    float a_r = 0.f, s_r = 0.f;
    float hbuf[4];
    #pragma unroll
    for (int k = 0; k < 4; ++k)
        hbuf[k] = valid ? hcol[(size_t)k * HH] : 0.f;

    for (int t = 0; t < LQ; t += 4) {
        float hn[4];
        #pragma unroll
        for (int k = 0; k < 4; ++k)
            hn[k] = valid ? hcol[(size_t)(t + 4 + k) * HH] : 0.f;
        #pragma unroll
        for (int k = 0; k < 4; ++k) {
            float a = salpha[t + k];
            float h = hbuf[k];
            float a_a = a + a_r;
            float rem = 1.0f - a_r;
            float s_a_nf = s_r + a * h;
            float s_a;
            if (a_a >= 1.0f) {
                float a_r_f = a - rem;
                s_a = s_r + rem * h;
                a_r = a_r_f;
                s_r = a_r_f * h;
            } else {
                a_r = a_a; s_a = s_a_nf; s_r = s_a_nf;
            }
            g_sa[obase + (size_t)(t + k) * HH] = __float2half_rn(s_a);
        }
        #pragma unroll
        for (int k = 0; k < 4; ++k) hbuf[k] = hn[k];
    }
    __syncthreads();
    if (tid == 0) { __threadfence(); atomicAdd(&g_scan_ready[b], 1); }
}

__device__ __noinline__ void do_nhat(float* out) {
    if (threadIdx.x == 0) {
        float s = 0.f;
        for (int b = 0; b < BB; ++b) {
            while (ld_acquire(&g_alpha_ready[b]) < 1) __nanosleep(128);
            s += g_nhat_part[b];
        }
        out[NHAT_OFF] = s;
    }
    __syncthreads();
}

// ---------------------------------------------------------------------------
// Mega persistent kernel: prelude units + fused double-GEMM, one launch.
// ---------------------------------------------------------------------------
#define KCH 64
#define NCHUNK (HH / KCH)            /* 12 */
#define MATB 16384
#define STAGEB 32768
#define NSTAGE 3
#define SOFF 1024
#define SMEM_SZ (SOFF + NSTAGE * STAGEB)   /* 99328 */

__device__ __forceinline__ void issue_chunk(uint32_t sb,
    const CUtensorMap* mA, const CUtensorMap* mB, int c, int row0, int col0) {
    int s = c % NSTAGE;
    uint32_t st = sb + SOFF + s * STAGEB;
    MBAR_EXPECT_TX(sb + s * 8, STAGEB);
    TMA2D(st,        mA, c * KCH, row0, sb + s * 8);
    TMA2D(st + MATB, mB, c * KCH, col0, sb + s * 8);
}

__global__ void __launch_bounds__(256, 2)
mega_kernel(const __grid_constant__ CUtensorMap tmA1,
            const __grid_constant__ CUtensorMap tmB1,
            const __grid_constant__ CUtensorMap tmA2,
            const __grid_constant__ CUtensorMap tmB2,
            const float* __restrict__ hs, const int* __restrict__ lengths,
            const float* __restrict__ W1, const float* __restrict__ W2,
            const float* __restrict__ b1, const float* __restrict__ b2,
            float* __restrict__ out,
            const float* __restrict__ bert, const float* __restrict__ mixu) {
    extern __shared__ __align__(1024) char smem[];
    uint32_t sb = smem_u32(smem);
    int* sh_t = (int*)(smem + 32);
    int* sh_flag = (int*)(smem + 36);
    int tid = threadIdx.x, lane = tid & 31, wid = tid >> 5;
    int wr = wid >> 2, wc = wid & 3;

    if (tid == 0) {
        #pragma unroll
        for (int s = 0; s < NSTAGE; ++s) MBAR_INIT(sb + s * 8, 1);
        *sh_t = atomicAdd(&g_tilectr, 1);
    }
    __syncthreads();

    int a_row = lane & 15;
    int a_un  = lane >> 4;
    int b_row = (lane & 7) + ((lane & 16) >> 1);
    int b_un  = (lane & 8) >> 3;
    int tr = lane >> 2;
    int tc = (lane & 3) * 2;

    int unit = *sh_t;
    int preissued = -1;

    while (unit < U_TOTAL) {
        if (unit < U_GEMM0) {
            if (unit < U_SCAN0) {
                do_alpha(hs, lengths, unit, smem);
            } else if (unit < U_WT0) {
                int s = unit - U_SCAN0;
                do_scan(hs, s / 3, s % 3, smem);
            } else if (unit < U_NHAT) {
                int w = unit - U_WT0;
                do_wtrans(W1, W2, w / 96, (w % 96) >> 2, w & 3, smem);
            } else {
                do_nhat(out);
            }
            __syncthreads();
            if (tid == 0) *sh_t = atomicAdd(&g_tilectr, 1);
            __syncthreads();
            unit = *sh_t;
            continue;
        }

        int tile = unit - U_GEMM0;
        int is1 = (tile < TILES1);
        int u = is1 ? tile : tile - TILES1;
        int rb = u / NCB, cb = u % NCB;
        int row0 = rb * 128, col0 = cb * 128;
        const CUtensorMap* mA = is1 ? &tmA1 : &tmA2;
        const CUtensorMap* mB = is1 ? &tmB1 : &tmB2;

        if (preissued != unit) {
            if (tid == 0) {
                if (is1) {
                    while (ld_acquire(&g_wt_ready[0]) < 96) __nanosleep(128);
                    int b0 = row0 / 400, b1e = (row0 + 127) / 400;
                    for (int b = b0; b <= b1e; ++b)
                        while (ld_acquire(&g_scan_ready[b]) < 3) __nanosleep(128);
                } else {
                    while (ld_acquire(&g_wt_ready[1]) < 96) __nanosleep(128);
                    while (ld_acquire(&g_ready[rb]) < NCB) __nanosleep(256);
                }
            }
            __syncthreads();
            if (tid == 0) {
                issue_chunk(sb, mA, mB, 0, row0, col0);
                issue_chunk(sb, mA, mB, 1, row0, col0);
            }
        }

        float acc[4][4][4];
        #pragma unroll
        for (int i = 0; i < 4; ++i)
            #pragma unroll
            for (int j = 0; j < 4; ++j)
                #pragma unroll
                for (int d = 0; d < 4; ++d) acc[i][j][d] = 0.f;

        for (int i = 0; i < NCHUNK; ++i) {
            if (tid == 0 && i + 2 < NCHUNK)
                issue_chunk(sb, mA, mB, i + 2, row0, col0);
            MBAR_WAIT(sb + (i % NSTAGE) * 8, (i / NSTAGE) & 1);

            uint32_t base = sb + SOFF + (i % NSTAGE) * STAGEB;
            #pragma unroll
            for (int kk = 0; kk < KCH; kk += 16) {
                uint32_t ah[4][4], bh[4][2];
                #pragma unroll
                for (int m = 0; m < 4; ++m) {
                    int r = wr * 64 + m * 16 + a_row;
                    int un = (kk >> 3) + a_un;
                    uint32_t off = base + r * 128 + ((un ^ (r & 7)) << 4);
                    LDM4(ah[m], off);
                }
                #pragma unroll
                for (int jp = 0; jp < 2; ++jp) {
                    int r = wc * 32 + jp * 16 + b_row;
                    int un = (kk >> 3) + b_un;
                    uint32_t off = base + MATB + r * 128 + ((un ^ (r & 7)) << 4);
                    uint32_t t0[4];
                    LDM4(t0, off);
                    bh[2*jp][0] = t0[0]; bh[2*jp][1] = t0[1];
                    bh[2*jp+1][0] = t0[2]; bh[2*jp+1][1] = t0[3];
                }
                #pragma unroll
                for (int m = 0; m < 4; ++m)
                    #pragma unroll
                    for (int j = 0; j < 4; ++j)
                        MMAH(acc[m][j], ah[m], bh[j]);
            }
            __syncthreads();
        }

        // claim next unit; pre-issue its prologue if it's ANY GEMM tile whose
        // deps are already satisfied (non-blocking check, smem-broadcast;
        // flag 1 = GEMM1 maps, 2 = GEMM2 maps).
        if (tid == 0) *sh_t = atomicAdd(&g_tilectr, 1);
        __syncthreads();
        int ntu = *sh_t;
        if (tid == 0) {
            int ok = 0;
            if (ntu >= U_GEMM0 && ntu < U_TOTAL) {
                int ntile = ntu - U_GEMM0;
                if (ntile < TILES1) {
                    int nrb = ntile / NCB;
                    ok = (ld_acquire(&g_wt_ready[0]) >= 96) ? 1 : 0;
                    if (ok) {
                        int b0 = (nrb * 128) / 400, b1e = (nrb * 128 + 127) / 400;
                        for (int b = b0; b <= b1e; ++b)
                            if (ld_acquire(&g_scan_ready[b]) < 3) { ok = 0; break; }
                    }
                } else {
                    int nrb = (ntile - TILES1) / NCB;
                    if (ld_acquire(&g_wt_ready[1]) >= 96 &&
                        ld_acquire(&g_ready[nrb]) >= NCB)
                        ok = 2;
                }
            }
            *sh_flag = ok;
        }
        __syncthreads();
        int flag = *sh_flag;
        preissued = -1;
        if (flag) {
            if (tid == 0) {
                int ntile = ntu - U_GEMM0;
                const CUtensorMap* nA, *nB;
                int nrb, ncb;
                if (flag == 1) {
                    nrb = ntile / NCB; ncb = ntile % NCB;
                    nA = &tmA1; nB = &tmB1;
                } else {
                    int t2 = ntile - TILES1;
                    nrb = t2 / NCB; ncb = t2 % NCB;
                    nA = &tmA2; nB = &tmB2;
                }
                issue_chunk(sb, nA, nB, 0, nrb * 128, ncb * 128);
                issue_chunk(sb, nA, nB, 1, nrb * 128, ncb * 128);
            }
            preissued = ntu;
        }

        // ---- epilogue ----
        const float* bias = is1 ? b1 : b2;
        float* fcout = out + FC_OFF;
        #pragma unroll
        for (int m = 0; m < 4; ++m) {
            #pragma unroll
            for (int half = 0; half < 2; ++half) {
                int row = row0 + wr * 64 + m * 16 + half * 8 + tr;
                float msk = 0.f;
                if (!is1) msk = (mixu[row] < P_MIX_C) ? 1.f : 0.f;
                #pragma unroll
                for (int j = 0; j < 4; ++j) {
                    int col = col0 + wc * 32 + j * 8 + tc;
                    float v0 = acc[m][j][half * 2 + 0] + bias[col];
                    float v1 = acc[m][j][half * 2 + 1] + bias[col + 1];
                    size_t idx = (size_t)row * HH + col;
                    if (is1) {
                        v0 = fmaxf(v0, 0.f); v1 = fmaxf(v1, 0.f);
                        *(uint32_t*)(g_y1 + idx) =
                            pack2h(__float2half_rn(v0), __float2half_rn(v1));
                    } else {
                        float2 fcv = make_float2(v0, v1);
                        *(float2*)(fcout + idx) = fcv;
                        float2 bm = fcv;
                        if (msk != 0.f) bm = *(const float2*)(bert + idx);
                        *(float2*)(out + idx) = bm;
                    }
                }
            }
        }

        if (is1) {                       // cumulative release: sync -> tid0 fence+add
            __syncthreads();
            if (tid == 0) { __threadfence(); atomicAdd(&g_ready[rb], 1); }
        }
        unit = ntu;
    }
}

// ---------------------------------------------------------------------------
typedef CUresult (*TmEncodeFn)(CUtensorMap*, CUtensorMapDataType, cuuint32_t,
                               void*, const cuuint64_t*, const cuuint64_t*,
                               const cuuint32_t*, const cuuint32_t*,
                               CUtensorMapInterleave, CUtensorMapSwizzle,
                               CUtensorMapL2promotion, CUtensorMapFloatOOBfill);

static void encode_map(TmEncodeFn fn, CUtensorMap* m, void* base, cuuint64_t rows) {
    cuuint64_t dims[2]    = {HH, rows};
    cuuint64_t strides[1] = {HH * sizeof(__half)};
    cuuint32_t box[2]     = {KCH, 128};
    cuuint32_t es[2]      = {1, 1};
    fn(m, CU_TENSOR_MAP_DATA_TYPE_FLOAT16, 2, base, dims, strides, box, es,
       CU_TENSOR_MAP_INTERLEAVE_NONE, CU_TENSOR_MAP_SWIZZLE_128B,
       CU_TENSOR_MAP_L2_PROMOTION_L2_128B, CU_TENSOR_MAP_FLOAT_OOB_FILL_NONE);
}

extern "C" void kernel_launch(void* const* d_in, const int* in_sizes, int n_in,
                              void* d_out, int out_size) {
    const float* hs      = (const float*)d_in[0];
    const int*   lengths = (const int*)  d_in[1];
    const float* W1      = (const float*)d_in[2];
    const float* b1      = (const float*)d_in[3];
    const float* W2      = (const float*)d_in[4];
    const float* b2      = (const float*)d_in[5];
    const float* bert    = (const float*)d_in[6];
    const float* mixu    = (const float*)d_in[7];
    float* out = (float*)d_out;

    __half *sa, *y1, *w1t, *w2t;
    cudaGetSymbolAddress((void**)&sa, g_sa);
    cudaGetSymbolAddress((void**)&y1, g_y1);
    cudaGetSymbolAddress((void**)&w1t, g_w1t);
    cudaGetSymbolAddress((void**)&w2t, g_w2t);

    void* fnp = nullptr;
    cudaDriverEntryPointQueryResult qr;
    cudaGetDriverEntryPoint("cuTensorMapEncodeTiled", &fnp,
                            cudaEnableDefault, &qr);
    TmEncodeFn enc = (TmEncodeFn)fnp;
    CUtensorMap tmA1, tmB1, tmA2, tmB2;
    encode_map(enc, &tmA1, sa,  MM);
    encode_map(enc, &tmB1, w1t, HH);
    encode_map(enc, &tmA2, y1,  MM);
    encode_map(enc, &tmB2, w2t, HH);

    cudaFuncSetAttribute(mega_kernel, cudaFuncAttributeMaxDynamicSharedMemorySize, SMEM_SZ);

    reset_kernel<<<1, 128>>>();
    mega_kernel<<<NCTA, 256, SMEM_SZ>>>(
        tmA1, tmB1, tmA2, tmB2,
        hs, lengths, W1, W2, b1, b2,
        out, bert, mixu);
}